// round 2
// baseline (speedup 1.0000x reference)
#include <cuda_runtime.h>
#include <cstdint>
#include <cfloat>

// Problem constants (shapes are fixed by this dataset)
#define NMAX 100000
#define BMAX 64
#define DD   256
#define TT   4
#define HH   32
#define CH   512   // entities per block in hamming kernel

// ---------------- scratch (static __device__, no allocation) ----------------
__device__ float         g_targets[BMAX * DD];
__device__ unsigned      g_tbits[BMAX * 4];
__device__ unsigned      g_abits[NMAX * 4];
__device__ unsigned char g_dist[(size_t)BMAX * NMAX];     // [b][n]
__device__ unsigned char g_dist_t[(size_t)NMAX * BMAX];   // [n][b]
__device__ unsigned      g_hist[BMAX * 129];
__device__ int           g_dstar[BMAX];
__device__ int           g_istar[BMAX];
__device__ float         g_scores[(size_t)BMAX * NMAX];   // [b][n]

// ---------------- K0: targets, target hash bits, zero histograms ------------
__global__ void k0_targets(const int* __restrict__ head,
                           const int* __restrict__ rel,
                           const float* __restrict__ eemb,
                           const float* __restrict__ remb,
                           const float* __restrict__ proj)
{
    __shared__ float tgt[DD];
    int b = blockIdx.x, tid = threadIdx.x;
    int hh = head[b], rr = rel[b];
    for (int d = tid; d < DD; d += blockDim.x) {
        float v = eemb[(size_t)hh * DD + d] * remb[(size_t)rr * DD + d];
        tgt[d] = v;
        g_targets[b * DD + d] = v;
    }
    for (int i = tid; i < 129; i += blockDim.x) g_hist[b * 129 + i] = 0u;
    __syncthreads();

    int t = tid >> 5, lane = tid & 31;     // 128 threads -> (t, h)
    const float* pp = proj + (size_t)t * DD * HH + lane;
    float acc = 0.f;
#pragma unroll 8
    for (int d = 0; d < DD; d++) acc += tgt[d] * pp[d * HH];
    unsigned w = __ballot_sync(0xffffffffu, acc > 0.f);
    if (lane == 0) g_tbits[b * 4 + t] = w;
}

// ---------------- K1: entity hash bits (the big GEMM-ish kernel) ------------
// smem: proj reorganized to [d][j=t*32+h] (128KB) + transposed 16-entity tile.
__global__ __launch_bounds__(256, 1)
void k1_entity_bits(const float* __restrict__ eemb,
                    const float* __restrict__ proj, int N)
{
    extern __shared__ float sm[];
    float* projs = sm;               // 256*128 = 32768 floats
    float* ebuf  = sm + 32768;       // [256][20] (16 entities, padded)

    int tid  = threadIdx.x;
    int j    = tid & 127;            // hash column 0..127
    int g    = tid >> 7;             // entity group 0/1
    int t    = j >> 5;
    int lane = tid & 31;

    // stage projection: proj[t][d][h] -> projs[d*128 + t*32 + h]
    for (int i = tid; i < TT * DD * HH; i += 256) {
        int tt = i >> 13, d = (i >> 5) & 255, h = i & 31;
        projs[d * 128 + tt * 32 + h] = proj[i];
    }

    int per = (N + gridDim.x - 1) / gridDim.x;
    int b0  = blockIdx.x * per;
    int b1  = min(N, b0 + per);
    __syncthreads();

    for (int base = b0; base < b1; base += 16) {
        int cnt = min(16, b1 - base);
        // stage 16 entity rows, transposed: ebuf[d][row]
        for (int idx = tid; idx < 16 * DD; idx += 256) {
            int row = idx >> 8, d = idx & 255;
            float v = (row < cnt) ? eemb[(size_t)(base + row) * DD + d] : 0.f;
            ebuf[d * 20 + row] = v;
        }
        __syncthreads();

        float acc[8] = {0,0,0,0,0,0,0,0};
#pragma unroll 4
        for (int d = 0; d < DD; d++) {
            float p = projs[d * 128 + j];
            const float4* eb = (const float4*)(ebuf + d * 20 + g * 8);
            float4 a = eb[0], c = eb[1];
            acc[0] += a.x * p; acc[1] += a.y * p;
            acc[2] += a.z * p; acc[3] += a.w * p;
            acc[4] += c.x * p; acc[5] += c.y * p;
            acc[6] += c.z * p; acc[7] += c.w * p;
        }
#pragma unroll
        for (int e = 0; e < 8; e++) {
            unsigned w = __ballot_sync(0xffffffffu, acc[e] > 0.f);
            int li = g * 8 + e;
            if (lane == 0 && li < cnt)
                g_abits[(size_t)(base + li) * 4 + t] = w;
        }
        __syncthreads();  // ebuf reuse
    }
}

// ---------------- K2: hamming distances + per-query histograms --------------
__global__ void k2_hamming(int N)
{
    extern __shared__ unsigned char smraw[];
    unsigned*      sab   = (unsigned*)smraw;                          // 512*4 u32
    unsigned*      shist = (unsigned*)(smraw + CH * 16);              // 64*132 u32
    unsigned char* sdist = smraw + CH * 16 + BMAX * 132 * 4;          // [64][512]

    int tid  = threadIdx.x;
    int base = blockIdx.x * CH;
    int cnt  = min(CH, N - base);

    for (int i = tid; i < BMAX * 132; i += blockDim.x) shist[i] = 0u;
    for (int i = tid; i < cnt * 4; i += blockDim.x) sab[i] = g_abits[(size_t)base * 4 + i];
    __syncthreads();

    int b = tid & 63, g = tid >> 6;
    unsigned t0 = g_tbits[b * 4 + 0], t1 = g_tbits[b * 4 + 1];
    unsigned t2 = g_tbits[b * 4 + 2], t3 = g_tbits[b * 4 + 3];

    for (int i = g; i < cnt; i += 4) {
        unsigned d = __popc(sab[i * 4 + 0] ^ t0) + __popc(sab[i * 4 + 1] ^ t1)
                   + __popc(sab[i * 4 + 2] ^ t2) + __popc(sab[i * 4 + 3] ^ t3);
        atomicAdd(&shist[b * 132 + d], 1u);
        sdist[b * CH + i] = (unsigned char)d;
    }
    __syncthreads();

    // write [b][n]
    for (int idx = tid; idx < BMAX * CH; idx += blockDim.x) {
        int bb = idx >> 9, i = idx & (CH - 1);
        if (i < cnt) g_dist[(size_t)bb * N + base + i] = sdist[idx];
    }
    // write [n][b]
    for (int idx = tid; idx < BMAX * CH; idx += blockDim.x) {
        int i = idx >> 6, bb = idx & 63;
        if (i < cnt) g_dist_t[(size_t)(base + i) * BMAX + bb] = sdist[bb * CH + i];
    }
    // flush histogram
    for (int idx = tid; idx < BMAX * 129; idx += blockDim.x) {
        int bb = idx / 129, d2 = idx % 129;
        unsigned v = shist[bb * 132 + d2];
        if (v) atomicAdd(&g_hist[idx], v);
    }
}

// ---------------- K3: per-query threshold d*, r, and index cutoff I* --------
__global__ void k3_threshold(int N, int CAND)
{
    int b = blockIdx.x, tid = threadIdx.x;
    __shared__ int s_dstar, s_r, s_ist;
    __shared__ unsigned char flags[1024];

    if (tid == 0) {
        unsigned cum = 0;
        for (int d = 0; d <= 128; d++) {
            unsigned h = g_hist[b * 129 + d];
            if (cum + h >= (unsigned)CAND) { s_dstar = d; s_r = CAND - (int)cum; break; }
            cum += h;
        }
        s_ist = -1;
    }
    __syncthreads();
    int dstar = s_dstar, r = s_r;
    const unsigned char* dd = g_dist + (size_t)b * N;

    int run = 0;
    for (int base = 0; base < N; base += blockDim.x) {
        int n = base + tid;
        int f = (n < N && dd[n] == (unsigned char)dstar) ? 1 : 0;
        int cnt = __syncthreads_count(f);
        if (run + cnt >= r) {
            flags[tid] = (unsigned char)f;
            __syncthreads();
            if (tid == 0) {
                int need = r - run, c = 0, i = 0;
                for (;; i++) { c += flags[i]; if (c == need) break; }
                s_ist = base + i;
            }
            __syncthreads();
            break;
        }
        run += cnt;
    }
    if (tid == 0) { g_dstar[b] = dstar; g_istar[b] = s_ist; }
}

// ---------------- K4: candidate scores (dense [B][N], -inf elsewhere) -------
__global__ __launch_bounds__(256)
void k4_scores(const float* __restrict__ eemb, int N)
{
    extern __shared__ float sm4[];
    float* st   = sm4;                       // targets 64*256
    float* tile = sm4 + BMAX * DD;           // [64][32]
    int*   ds   = (int*)(tile + BMAX * 32);  // 64
    int*   is_  = ds + BMAX;                 // 64

    int tid = threadIdx.x;
    for (int i = tid; i < BMAX * DD; i += blockDim.x) st[i] = g_targets[i];
    if (tid < BMAX) { ds[tid] = g_dstar[tid]; is_[tid] = g_istar[tid]; }
    for (int i = tid; i < BMAX * 32; i += blockDim.x) tile[i] = -FLT_MAX;
    __syncthreads();

    int base = blockIdx.x * 32;
    int w = tid >> 5, lane = tid & 31;

    for (int e = 0; e < 4; e++) {
        int i = w * 4 + e;
        int n = base + i;
        if (n >= N) continue;  // uniform per warp
        float4 r0 = *(const float4*)(eemb + (size_t)n * DD + lane * 8);
        float4 r1 = *(const float4*)(eemb + (size_t)n * DD + lane * 8 + 4);
        unsigned char d0 = g_dist_t[(size_t)n * BMAX + lane];
        unsigned char d1 = g_dist_t[(size_t)n * BMAX + 32 + lane];
        int b0 = lane, b1 = lane + 32;
        bool f0 = (d0 < ds[b0]) || (d0 == ds[b0] && n <= is_[b0]);
        bool f1 = (d1 < ds[b1]) || (d1 == ds[b1] && n <= is_[b1]);
        unsigned m0 = __ballot_sync(0xffffffffu, f0);
        unsigned m1 = __ballot_sync(0xffffffffu, f1);

        while (m0) {
            int b = __ffs(m0) - 1; m0 &= m0 - 1;
            const float4* tp = (const float4*)(st + b * DD + lane * 8);
            float4 t0 = tp[0], t1 = tp[1];
            float s = r0.x * t0.x + r0.y * t0.y + r0.z * t0.z + r0.w * t0.w
                    + r1.x * t1.x + r1.y * t1.y + r1.z * t1.z + r1.w * t1.w;
#pragma unroll
            for (int off = 16; off; off >>= 1) s += __shfl_xor_sync(0xffffffffu, s, off);
            if (lane == 0) tile[b * 32 + i] = s;
        }
        while (m1) {
            int b = 32 + __ffs(m1) - 1; m1 &= m1 - 1;
            const float4* tp = (const float4*)(st + b * DD + lane * 8);
            float4 t0 = tp[0], t1 = tp[1];
            float s = r0.x * t0.x + r0.y * t0.y + r0.z * t0.z + r0.w * t0.w
                    + r1.x * t1.x + r1.y * t1.y + r1.z * t1.z + r1.w * t1.w;
#pragma unroll
            for (int off = 16; off; off >>= 1) s += __shfl_xor_sync(0xffffffffu, s, off);
            if (lane == 0) tile[b * 32 + i] = s;
        }
    }
    __syncthreads();
    for (int idx = tid; idx < BMAX * 32; idx += blockDim.x) {
        int bb = idx >> 5, i = idx & 31;
        int n = base + i;
        if (n < N) g_scores[(size_t)bb * N + n] = tile[idx];
    }
}

// ---------------- K5: iterative top-k (stable: ties -> smaller index) -------
__global__ void k5_topk(const int* __restrict__ kptr, float* __restrict__ out,
                        int N, int half)
{
    int b = blockIdx.x, tid = threadIdx.x;
    int kk = kptr[0];
    __shared__ float sv[32];
    __shared__ int   si[32];
    float* sc = g_scores + (size_t)b * N;
    int w = tid >> 5, lane = tid & 31;
    int nw = blockDim.x >> 5;

    for (int p = 0; p < kk; p++) {
        float bv = -FLT_MAX; int bi = 0x7fffffff;
        for (int n = tid; n < N; n += blockDim.x) {
            float s = sc[n];
            if (s > bv || (s == bv && n < bi)) { bv = s; bi = n; }
        }
#pragma unroll
        for (int off = 16; off; off >>= 1) {
            float ov = __shfl_down_sync(0xffffffffu, bv, off);
            int   oi = __shfl_down_sync(0xffffffffu, bi, off);
            if (ov > bv || (ov == bv && oi < bi)) { bv = ov; bi = oi; }
        }
        if (lane == 0) { sv[w] = bv; si[w] = bi; }
        __syncthreads();
        if (w == 0) {
            bv = (lane < nw) ? sv[lane] : -FLT_MAX;
            bi = (lane < nw) ? si[lane] : 0x7fffffff;
#pragma unroll
            for (int off = 16; off; off >>= 1) {
                float ov = __shfl_down_sync(0xffffffffu, bv, off);
                int   oi = __shfl_down_sync(0xffffffffu, bi, off);
                if (ov > bv || (ov == bv && oi < bi)) { bv = ov; bi = oi; }
            }
            if (lane == 0) {
                out[b * kk + p]        = (float)bi;   // indices (first half)
                out[half + b * kk + p] = bv;          // scores  (second half)
                sc[bi] = -FLT_MAX;
            }
        }
        __syncthreads();
    }
}

// ---------------- launch --------------------------------------------------
extern "C" void kernel_launch(void* const* d_in, const int* in_sizes, int n_in,
                              void* d_out, int out_size)
{
    const int*   head = (const int*)d_in[0];
    const int*   rel  = (const int*)d_in[1];
    const float* eemb = (const float*)d_in[2];
    const float* remb = (const float*)d_in[3];
    const float* proj = (const float*)d_in[4];
    const int*   kptr = (const int*)d_in[5];

    int B = in_sizes[0];
    int N = in_sizes[2] / DD;
    int CAND = N / 10; if (CAND < 100) CAND = 100;

    // dynamic smem limits (idempotent; legal during capture: not stream ops)
    cudaFuncSetAttribute(k1_entity_bits, cudaFuncAttributeMaxDynamicSharedMemorySize, 160 * 1024);
    cudaFuncSetAttribute(k2_hamming,     cudaFuncAttributeMaxDynamicSharedMemorySize, 80 * 1024);
    cudaFuncSetAttribute(k4_scores,      cudaFuncAttributeMaxDynamicSharedMemorySize, 80 * 1024);

    size_t k1_smem = (32768 + 256 * 20) * sizeof(float);          // 151552
    size_t k2_smem = CH * 16 + BMAX * 132 * 4 + (size_t)BMAX * CH; // 74752
    size_t k4_smem = (BMAX * DD + BMAX * 32) * sizeof(float) + 2 * BMAX * sizeof(int);

    k0_targets<<<B, 128>>>(head, rel, eemb, remb, proj);
    k1_entity_bits<<<148, 256, k1_smem>>>(eemb, proj, N);
    k2_hamming<<<(N + CH - 1) / CH, 256, k2_smem>>>(N);
    k3_threshold<<<B, 1024>>>(N, CAND);
    k4_scores<<<(N + 31) / 32, 256, k4_smem>>>(eemb, N);
    k5_topk<<<B, 1024>>>(kptr, (float*)d_out, N, out_size / 2);
}